// round 8
// baseline (speedup 1.0000x reference)
#include <cuda_runtime.h>
#include <cuda_fp16.h>
#include <cstdint>

#define BB 64
#define PP 1024
#define TT 1024
#define NITER 50
#define HALFP 512      // p-rows per cluster CTA

typedef unsigned long long u64;

// fp16 Gibbs kernel, layout [b][p][t], t contiguous. 134 MB.
__device__ __align__(16) __half g_Kh[(size_t)BB * PP * TT];
__device__ __align__(16) float  g_u[BB * PP];
__device__ __align__(16) float  g_v[BB * TT];

// ---- f32x2 packed helpers (sm_103a FFMA2 path) ----
__device__ __forceinline__ u64 f32x2_pack(float lo, float hi) {
    u64 r; asm("mov.b64 %0, {%1, %2};" : "=l"(r) : "f"(lo), "f"(hi)); return r;
}
__device__ __forceinline__ float2 f32x2_unpack(u64 a) {
    float2 f; asm("mov.b64 {%0, %1}, %2;" : "=f"(f.x), "=f"(f.y) : "l"(a)); return f;
}
__device__ __forceinline__ u64 ffma2(u64 a, u64 b, u64 c) {
    u64 d; asm("fma.rn.f32x2 %0, %1, %2, %3;" : "=l"(d) : "l"(a), "l"(b), "l"(c)); return d;
}
__device__ __forceinline__ u64 fadd2(u64 a, u64 b) {
    u64 d; asm("add.rn.f32x2 %0, %1, %2;" : "=l"(d) : "l"(a), "l"(b)); return d;
}
__device__ __forceinline__ u64 h2_to_f32x2(unsigned int h) {
    u64 r;
    asm("{\n\t"
        ".reg .b16 l, h;\n\t"
        ".reg .f32 fl, fh;\n\t"
        "mov.b32 {l, h}, %1;\n\t"
        "cvt.f32.f16 fl, l;\n\t"
        "cvt.f32.f16 fh, h;\n\t"
        "mov.b64 %0, {fl, fh};\n\t"
        "}" : "=l"(r) : "r"(h));
    return r;
}

// K = exp(-C/reg) -> fp16, 8 elems/thread.
__global__ void k_exp(const float* __restrict__ C, const float* __restrict__ reg) {
    const size_t i8 = (size_t)blockIdx.x * 256 + threadIdx.x;
    const float ninv = -1.0f / reg[0];
    const float4* __restrict__ C4 = (const float4*)C;
    const float4 a = C4[2 * i8];
    const float4 c = C4[2 * i8 + 1];
    uint4 pack;
    __half2* ph = reinterpret_cast<__half2*>(&pack);
    ph[0] = __floats2half2_rn(__expf(a.x * ninv), __expf(a.y * ninv));
    ph[1] = __floats2half2_rn(__expf(a.z * ninv), __expf(a.w * ninv));
    ph[2] = __floats2half2_rn(__expf(c.x * ninv), __expf(c.y * ninv));
    ph[3] = __floats2half2_rn(__expf(c.z * ninv), __expf(c.w * ninv));
    ((uint4*)g_Kh)[i8] = pack;
}

// Persistent fused Sinkhorn, cluster of 2 CTAs per batch (128 CTAs).
// One K pass per iteration; K converted ONCE per row; FFMA2 math;
// v in shared, warp-permuted float2 layout (conflict-free LDS.64).
// No software prefetch: 16 warps/SM hide latency; regs stay < 128.
//
// Permutation: entry e = q*32 + lane (q = 4*i + j). Entry e covers t-pair
// t0 = 2*g, t1 = 2*g+1 with g = 4*(lane + 32*i) + j.
__global__ void __launch_bounds__(512, 1) __cluster_dims__(2, 1, 1)
k_sinkhorn(const float* __restrict__ pred, const float* __restrict__ tgt) {
    __shared__ float2 vperm[512];         //  4 KB  permuted v
    __shared__ float2 buf2[8][512];       // 32 KB  warp-combine tree
    __shared__ float2 part_peer[2][512];  //  8 KB  DSMEM partials (parity)
    __shared__ float  pred_s[HALFP];      //  2 KB

    const int tid  = threadIdx.x;
    const int b    = blockIdx.x >> 1;
    const int r    = blockIdx.x & 1;
    const int peer = r ^ 1;
    const int wid  = tid >> 5;
    const int lane = tid & 31;

    // this thread's permuted t-pair
    const int q_e = tid >> 5;
    const int g_e = 4 * ((tid & 31) + 32 * (q_e >> 2)) + (q_e & 3);
    const int t0  = 2 * g_e;
    const int t1  = t0 + 1;

    pred_s[tid] = pred[b * PP + r * HALFP + tid];
    const float tgt0 = tgt[b * TT + t0];
    const float tgt1 = tgt[b * TT + t1];
    __syncthreads();

    const uint4* __restrict__ K4 =
        (const uint4*)(g_Kh + ((size_t)b * PP + (size_t)r * HALFP) * TT);
    const size_t rowbase0 = (size_t)(wid * 32) * 128 + lane;
    const u64* __restrict__ vp64 = (const u64*)vperm;

    for (int iter = 0; iter <= NITER; iter++) {
        u64 acc2[16];
#pragma unroll
        for (int q = 0; q < 16; q++) acc2[q] = 0ULL;   // (0.f, 0.f)

#pragma unroll 1
        for (int rr = 0; rr < 32; rr++) {
            const size_t base = rowbase0 + (size_t)rr * 128;
            const uint4 k0 = K4[base +  0];
            const uint4 k1 = K4[base + 32];
            const uint4 k2 = K4[base + 64];
            const uint4 k3 = K4[base + 96];

            u64 f[16];
            f[ 0] = h2_to_f32x2(k0.x); f[ 1] = h2_to_f32x2(k0.y);
            f[ 2] = h2_to_f32x2(k0.z); f[ 3] = h2_to_f32x2(k0.w);
            f[ 4] = h2_to_f32x2(k1.x); f[ 5] = h2_to_f32x2(k1.y);
            f[ 6] = h2_to_f32x2(k1.z); f[ 7] = h2_to_f32x2(k1.w);
            f[ 8] = h2_to_f32x2(k2.x); f[ 9] = h2_to_f32x2(k2.y);
            f[10] = h2_to_f32x2(k2.z); f[11] = h2_to_f32x2(k2.w);
            f[12] = h2_to_f32x2(k3.x); f[13] = h2_to_f32x2(k3.y);
            f[14] = h2_to_f32x2(k3.z); f[15] = h2_to_f32x2(k3.w);

            if (iter == 0) {
                // u = 1: accumulate K directly
#pragma unroll
                for (int q = 0; q < 16; q++)
                    acc2[q] = fadd2(acc2[q], f[q]);
            } else {
                // dot(K_p, v): two chains to halve serial latency
                u64 d2a = 0ULL, d2b = 0ULL;
#pragma unroll
                for (int q = 0; q < 8; q++) {
                    d2a = ffma2(f[q],     vp64[q * 32 + lane],        d2a);
                    d2b = ffma2(f[q + 8], vp64[(q + 8) * 32 + lane],  d2b);
                }
                const u64 d2 = fadd2(d2a, d2b);
                const float2 dd = f32x2_unpack(d2);
                float a = dd.x + dd.y;
#pragma unroll
                for (int o = 16; o; o >>= 1)
                    a += __shfl_xor_sync(0xFFFFFFFFu, a, o);

                const int p = wid * 32 + rr;
                const float up = __fdividef(pred_s[p], a);
                if (iter == NITER && lane == 0)
                    g_u[b * PP + r * HALFP + p] = up;

                const u64 up2 = f32x2_pack(up, up);
#pragma unroll
                for (int q = 0; q < 16; q++)
                    acc2[q] = ffma2(f[q], up2, acc2[q]);
            }
        }

        // combine 16 warps -> buf2[8][512] (two rounds), permuted layout
        if (wid < 8) {
            u64* __restrict__ dst = (u64*)&buf2[wid][0];
#pragma unroll
            for (int q = 0; q < 16; q++)
                dst[q * 32 + lane] = acc2[q];
        }
        __syncthreads();
        if (wid >= 8) {
            u64* __restrict__ dst = (u64*)&buf2[wid - 8][0];
#pragma unroll
            for (int q = 0; q < 16; q++) {
                const int e = q * 32 + lane;
                dst[e] = fadd2(dst[e], acc2[q]);
            }
        }
        __syncthreads();

        u64 s2 = 0ULL;
        const u64* __restrict__ bsrc = (const u64*)buf2;
#pragma unroll
        for (int w = 0; w < 8; w++)
            s2 = fadd2(s2, bsrc[w * 512 + tid]);
        const float2 s = f32x2_unpack(s2);

        // DSMEM exchange with peer CTA (parity double-buffer)
        const int par = iter & 1;
        {
            unsigned int l0 = (unsigned int)__cvta_generic_to_shared(&part_peer[par][tid]);
            unsigned int r0;
            asm volatile("mapa.shared::cluster.u32 %0, %1, %2;"
                         : "=r"(r0) : "r"(l0), "r"(peer));
            asm volatile("st.shared::cluster.b64 [%0], %1;"
                         :: "r"(r0), "l"(s2) : "memory");
        }
        asm volatile("barrier.cluster.arrive.aligned;" ::: "memory");
        asm volatile("barrier.cluster.wait.aligned;" ::: "memory");

        const float2 ppart = part_peer[par][tid];
        const float v0 = tgt0 / (s.x + ppart.x);
        const float v1 = tgt1 / (s.y + ppart.y);
        vperm[tid] = make_float2(v0, v1);
        __syncthreads();
    }

    if (r == 0) {
        const float2 vfin = vperm[tid];
        g_v[b * TT + t0] = vfin.x;
        g_v[b * TT + t1] = vfin.y;
    }
}

// Final: P = u * Kh * v  (fp16 K; 8 elems/thread).
__global__ void k_final(float* __restrict__ out) {
    const size_t i8 = (size_t)blockIdx.x * 256 + threadIdx.x;  // uint4 index
    const int row = (int)(i8 >> 7);          // b*1024 + p
    const int b   = row >> 10;
    const int t8  = (int)(i8 & 127);

    const float u = g_u[row];
    const uint4 kk = ((const uint4*)g_Kh)[i8];
    const float4* vr = (const float4*)(g_v + b * TT) + 2 * t8;
    const float4 va = vr[0];
    const float4 vb = vr[1];

    const __half2* h = (const __half2*)&kk;
    const float2 f0 = __half22float2(h[0]);
    const float2 f1 = __half22float2(h[1]);
    const float2 f2 = __half22float2(h[2]);
    const float2 f3 = __half22float2(h[3]);

    float4 o0, o1;
    o0.x = u * f0.x * va.x;  o0.y = u * f0.y * va.y;
    o0.z = u * f1.x * va.z;  o0.w = u * f1.y * va.w;
    o1.x = u * f2.x * vb.x;  o1.y = u * f2.y * vb.y;
    o1.z = u * f3.x * vb.z;  o1.w = u * f3.y * vb.w;

    float4* out4 = (float4*)out;
    out4[2 * i8 + 0] = o0;
    out4[2 * i8 + 1] = o1;
}

extern "C" void kernel_launch(void* const* d_in, const int* in_sizes, int n_in,
                              void* d_out, int out_size) {
    const float* pred = (const float*)d_in[0];
    const float* tgt  = (const float*)d_in[1];
    const float* C    = (const float*)d_in[2];
    const float* reg  = (const float*)d_in[3];
    float* out = (float*)d_out;

    const int n8 = (BB * PP * TT) / 8;

    k_exp<<<n8 / 256, 256>>>(C, reg);
    k_sinkhorn<<<2 * BB, 512>>>(pred, tgt);
    k_final<<<n8 / 256, 256>>>(out);
}

// round 9
// speedup vs baseline: 1.0341x; 1.0341x over previous
#include <cuda_runtime.h>
#include <cuda_fp16.h>
#include <cstdint>

#define BB 64
#define PP 1024
#define TT 1024
#define NITER 50
#define HALFP 512      // p-rows per cluster CTA

typedef unsigned long long u64;

// fp16 Gibbs kernel, layout [b][p][t], t contiguous. 134 MB.
__device__ __align__(16) __half g_Kh[(size_t)BB * PP * TT];
__device__ __align__(16) float  g_u[BB * PP];
__device__ __align__(16) float  g_v[BB * TT];

// ---- f32x2 packed helpers (sm_103a FFMA2 path) ----
__device__ __forceinline__ u64 f32x2_pack(float lo, float hi) {
    u64 r; asm("mov.b64 %0, {%1, %2};" : "=l"(r) : "f"(lo), "f"(hi)); return r;
}
__device__ __forceinline__ float2 f32x2_unpack(u64 a) {
    float2 f; asm("mov.b64 {%0, %1}, %2;" : "=f"(f.x), "=f"(f.y) : "l"(a)); return f;
}
__device__ __forceinline__ u64 ffma2(u64 a, u64 b, u64 c) {
    u64 d; asm("fma.rn.f32x2 %0, %1, %2, %3;" : "=l"(d) : "l"(a), "l"(b), "l"(c)); return d;
}
__device__ __forceinline__ u64 fadd2(u64 a, u64 b) {
    u64 d; asm("add.rn.f32x2 %0, %1, %2;" : "=l"(d) : "l"(a), "l"(b)); return d;
}
__device__ __forceinline__ u64 h2_to_f32x2(unsigned int h) {
    u64 r;
    asm("{\n\t"
        ".reg .b16 l, h;\n\t"
        ".reg .f32 fl, fh;\n\t"
        "mov.b32 {l, h}, %1;\n\t"
        "cvt.f32.f16 fl, l;\n\t"
        "cvt.f32.f16 fh, h;\n\t"
        "mov.b64 %0, {fl, fh};\n\t"
        "}" : "=l"(r) : "r"(h));
    return r;
}

// K = exp(-C/reg) -> fp16, 8 elems/thread.
__global__ void k_exp(const float* __restrict__ C, const float* __restrict__ reg) {
    const size_t i8 = (size_t)blockIdx.x * 256 + threadIdx.x;
    const float ninv = -1.0f / reg[0];
    const float4* __restrict__ C4 = (const float4*)C;
    const float4 a = C4[2 * i8];
    const float4 c = C4[2 * i8 + 1];
    uint4 pack;
    __half2* ph = reinterpret_cast<__half2*>(&pack);
    ph[0] = __floats2half2_rn(__expf(a.x * ninv), __expf(a.y * ninv));
    ph[1] = __floats2half2_rn(__expf(a.z * ninv), __expf(a.w * ninv));
    ph[2] = __floats2half2_rn(__expf(c.x * ninv), __expf(c.y * ninv));
    ph[3] = __floats2half2_rn(__expf(c.z * ninv), __expf(c.w * ninv));
    ((uint4*)g_Kh)[i8] = pack;
}

// Persistent fused Sinkhorn, cluster of 2 CTAs per batch (128 CTAs).
// One K pass per iteration. v in REGISTERS (loaded from shared once per
// iteration); K converted once per row; FFMA2 math; no LDS in the hot loop.
//
// Permutation: entry e = q*32 + lane (q = 4*i + j). Entry e covers t-pair
// t0 = 2*g, t1 = 2*g+1 with g = 4*(lane + 32*i) + j.
__global__ void __launch_bounds__(512, 1) __cluster_dims__(2, 1, 1)
k_sinkhorn(const float* __restrict__ pred, const float* __restrict__ tgt) {
    __shared__ float2 vperm[512];         //  4 KB  permuted v
    __shared__ float2 buf2[8][512];       // 32 KB  warp-combine tree
    __shared__ float2 part_peer[2][512];  //  8 KB  DSMEM partials (parity)
    __shared__ float  pred_s[HALFP];      //  2 KB

    const int tid  = threadIdx.x;
    const int b    = blockIdx.x >> 1;
    const int r    = blockIdx.x & 1;
    const int peer = r ^ 1;
    const int wid  = tid >> 5;
    const int lane = tid & 31;

    // this thread's permuted t-pair
    const int q_e = tid >> 5;
    const int g_e = 4 * ((tid & 31) + 32 * (q_e >> 2)) + (q_e & 3);
    const int t0  = 2 * g_e;
    const int t1  = t0 + 1;

    pred_s[tid] = pred[b * PP + r * HALFP + tid];
    const float tgt0 = tgt[b * TT + t0];
    const float tgt1 = tgt[b * TT + t1];
    __syncthreads();

    const uint4* __restrict__ K4 =
        (const uint4*)(g_Kh + ((size_t)b * PP + (size_t)r * HALFP) * TT);
    const size_t rowbase0 = (size_t)(wid * 32) * 128 + lane;
    const u64* __restrict__ vp64 = (const u64*)vperm;

    for (int iter = 0; iter <= NITER; iter++) {
        // v into registers, packed pairs (once per ITERATION, conflict-free)
        u64 vreg2[16];
        if (iter > 0) {
#pragma unroll
            for (int q = 0; q < 16; q++)
                vreg2[q] = vp64[q * 32 + lane];
        }

        u64 acc2[16];
#pragma unroll
        for (int q = 0; q < 16; q++) acc2[q] = 0ULL;   // (0.f, 0.f)

#pragma unroll 1
        for (int rr = 0; rr < 32; rr++) {
            const size_t base = rowbase0 + (size_t)rr * 128;
            const uint4 k0 = K4[base +  0];
            const uint4 k1 = K4[base + 32];
            const uint4 k2 = K4[base + 64];
            const uint4 k3 = K4[base + 96];

            u64 f[16];
            f[ 0] = h2_to_f32x2(k0.x); f[ 1] = h2_to_f32x2(k0.y);
            f[ 2] = h2_to_f32x2(k0.z); f[ 3] = h2_to_f32x2(k0.w);
            f[ 4] = h2_to_f32x2(k1.x); f[ 5] = h2_to_f32x2(k1.y);
            f[ 6] = h2_to_f32x2(k1.z); f[ 7] = h2_to_f32x2(k1.w);
            f[ 8] = h2_to_f32x2(k2.x); f[ 9] = h2_to_f32x2(k2.y);
            f[10] = h2_to_f32x2(k2.z); f[11] = h2_to_f32x2(k2.w);
            f[12] = h2_to_f32x2(k3.x); f[13] = h2_to_f32x2(k3.y);
            f[14] = h2_to_f32x2(k3.z); f[15] = h2_to_f32x2(k3.w);

            if (iter == 0) {
                // u = 1: accumulate K directly
#pragma unroll
                for (int q = 0; q < 16; q++)
                    acc2[q] = fadd2(acc2[q], f[q]);
            } else {
                // dot(K_p, v): two chains to halve serial latency
                u64 d2a = 0ULL, d2b = 0ULL;
#pragma unroll
                for (int q = 0; q < 8; q++) {
                    d2a = ffma2(f[q],     vreg2[q],     d2a);
                    d2b = ffma2(f[q + 8], vreg2[q + 8], d2b);
                }
                const u64 d2 = fadd2(d2a, d2b);
                const float2 dd = f32x2_unpack(d2);
                float a = dd.x + dd.y;
#pragma unroll
                for (int o = 16; o; o >>= 1)
                    a += __shfl_xor_sync(0xFFFFFFFFu, a, o);

                const int p = wid * 32 + rr;
                const float up = __fdividef(pred_s[p], a);
                if (iter == NITER && lane == 0)
                    g_u[b * PP + r * HALFP + p] = up;

                const u64 up2 = f32x2_pack(up, up);
#pragma unroll
                for (int q = 0; q < 16; q++)
                    acc2[q] = ffma2(f[q], up2, acc2[q]);
            }
        }

        // combine 16 warps -> buf2[8][512] (two rounds), permuted layout
        if (wid < 8) {
            u64* __restrict__ dst = (u64*)&buf2[wid][0];
#pragma unroll
            for (int q = 0; q < 16; q++)
                dst[q * 32 + lane] = acc2[q];
        }
        __syncthreads();
        if (wid >= 8) {
            u64* __restrict__ dst = (u64*)&buf2[wid - 8][0];
#pragma unroll
            for (int q = 0; q < 16; q++) {
                const int e = q * 32 + lane;
                dst[e] = fadd2(dst[e], acc2[q]);
            }
        }
        __syncthreads();

        u64 s2 = 0ULL;
        const u64* __restrict__ bsrc = (const u64*)buf2;
#pragma unroll
        for (int w = 0; w < 8; w++)
            s2 = fadd2(s2, bsrc[w * 512 + tid]);
        const float2 s = f32x2_unpack(s2);

        // DSMEM exchange with peer CTA (parity double-buffer)
        const int par = iter & 1;
        {
            unsigned int l0 = (unsigned int)__cvta_generic_to_shared(&part_peer[par][tid]);
            unsigned int r0;
            asm volatile("mapa.shared::cluster.u32 %0, %1, %2;"
                         : "=r"(r0) : "r"(l0), "r"(peer));
            asm volatile("st.shared::cluster.b64 [%0], %1;"
                         :: "r"(r0), "l"(s2) : "memory");
        }
        asm volatile("barrier.cluster.arrive.aligned;" ::: "memory");
        asm volatile("barrier.cluster.wait.aligned;" ::: "memory");

        const float2 ppart = part_peer[par][tid];
        const float v0 = tgt0 / (s.x + ppart.x);
        const float v1 = tgt1 / (s.y + ppart.y);
        vperm[tid] = make_float2(v0, v1);
        __syncthreads();
    }

    if (r == 0) {
        const float2 vfin = vperm[tid];
        g_v[b * TT + t0] = vfin.x;
        g_v[b * TT + t1] = vfin.y;
    }
}

// Final: P = u * Kh * v  (fp16 K; 8 elems/thread).
__global__ void k_final(float* __restrict__ out) {
    const size_t i8 = (size_t)blockIdx.x * 256 + threadIdx.x;  // uint4 index
    const int row = (int)(i8 >> 7);          // b*1024 + p
    const int b   = row >> 10;
    const int t8  = (int)(i8 & 127);

    const float u = g_u[row];
    const uint4 kk = ((const uint4*)g_Kh)[i8];
    const float4* vr = (const float4*)(g_v + b * TT) + 2 * t8;
    const float4 va = vr[0];
    const float4 vb = vr[1];

    const __half2* h = (const __half2*)&kk;
    const float2 f0 = __half22float2(h[0]);
    const float2 f1 = __half22float2(h[1]);
    const float2 f2 = __half22float2(h[2]);
    const float2 f3 = __half22float2(h[3]);

    float4 o0, o1;
    o0.x = u * f0.x * va.x;  o0.y = u * f0.y * va.y;
    o0.z = u * f1.x * va.z;  o0.w = u * f1.y * va.w;
    o1.x = u * f2.x * vb.x;  o1.y = u * f2.y * vb.y;
    o1.z = u * f3.x * vb.z;  o1.w = u * f3.y * vb.w;

    float4* out4 = (float4*)out;
    out4[2 * i8 + 0] = o0;
    out4[2 * i8 + 1] = o1;
}

extern "C" void kernel_launch(void* const* d_in, const int* in_sizes, int n_in,
                              void* d_out, int out_size) {
    const float* pred = (const float*)d_in[0];
    const float* tgt  = (const float*)d_in[1];
    const float* C    = (const float*)d_in[2];
    const float* reg  = (const float*)d_in[3];
    float* out = (float*)d_out;

    const int n8 = (BB * PP * TT) / 8;

    k_exp<<<n8 / 256, 256>>>(C, reg);
    k_sinkhorn<<<2 * BB, 512>>>(pred, tgt);
    k_final<<<n8 / 256, 256>>>(out);
}

// round 10
// speedup vs baseline: 1.1711x; 1.1325x over previous
#include <cuda_runtime.h>
#include <cstdint>

#define BB 64
#define PP 1024
#define TT 1024
#define NITER 50
#define HALFP 512      // p-rows per cluster CTA

// bf16 Gibbs kernel, layout [b][p][t], t contiguous. 134 MB.
// Stored as raw uint16 bf16 bits (manual RN-even; K in (0,1], always finite).
__device__ __align__(16) unsigned short g_Kb[(size_t)BB * PP * TT];
__device__ __align__(16) float g_u[BB * PP];
__device__ __align__(16) float g_v[BB * TT];

__device__ __forceinline__ unsigned int bf16pair(float a, float b) {
    unsigned int ua = __float_as_uint(a);
    unsigned int ub = __float_as_uint(b);
    ua = (ua + 0x7FFFu + ((ua >> 16) & 1u)) >> 16;   // RN-even
    ub = (ub + 0x7FFFu + ((ub >> 16) & 1u)) >> 16;
    return ua | (ub << 16);
}
// bf16x2 word -> two f32 (alu-pipe: SHF + LOP3)
__device__ __forceinline__ float bf_lo(unsigned int h) { return __int_as_float(h << 16); }
__device__ __forceinline__ float bf_hi(unsigned int h) { return __int_as_float(h & 0xFFFF0000u); }

// K = exp(-C/reg) -> bf16, 8 elems/thread.
__global__ void k_exp(const float* __restrict__ C, const float* __restrict__ reg) {
    const size_t i8 = (size_t)blockIdx.x * 256 + threadIdx.x;
    const float ninv = -1.0f / reg[0];
    const float4* __restrict__ C4 = (const float4*)C;
    const float4 a = C4[2 * i8];
    const float4 c = C4[2 * i8 + 1];
    uint4 pack;
    pack.x = bf16pair(__expf(a.x * ninv), __expf(a.y * ninv));
    pack.y = bf16pair(__expf(a.z * ninv), __expf(a.w * ninv));
    pack.z = bf16pair(__expf(c.x * ninv), __expf(c.y * ninv));
    pack.w = bf16pair(__expf(c.z * ninv), __expf(c.w * ninv));
    ((uint4*)g_Kb)[i8] = pack;
}

// Persistent fused Sinkhorn, cluster of 2 CTAs per batch (128 CTAs).
// One K pass per iteration; R6 structure (scalar FFMA, v in registers,
// row prefetch) with bf16 K whose f32 conversion is SHF/LOP3 on the ALU
// pipe, leaving the FMA pipe for 64 FFMA/row.
__global__ void __launch_bounds__(512, 1) __cluster_dims__(2, 1, 1)
k_sinkhorn(const float* __restrict__ pred, const float* __restrict__ tgt) {
    __shared__ float v_s[TT];             //  4 KB
    __shared__ float u_s[HALFP];          //  2 KB
    __shared__ float buf[8][TT];          // 32 KB warp-combine tree
    __shared__ float part_peer[2][TT];    //  8 KB DSMEM partials (parity)
    __shared__ float pred_s[HALFP];       //  2 KB

    const int tid  = threadIdx.x;
    const int b    = blockIdx.x >> 1;
    const int r    = blockIdx.x & 1;
    const int peer = r ^ 1;
    const int wid  = tid >> 5;
    const int lane = tid & 31;

    pred_s[tid] = pred[b * PP + r * HALFP + tid];
    const float tgt_a = tgt[b * TT + tid];
    const float tgt_b = tgt[b * TT + tid + 512];
    __syncthreads();

    const uint4* __restrict__ K4 =
        (const uint4*)(g_Kb + ((size_t)b * PP + (size_t)r * HALFP) * TT);
    const size_t row0 = (size_t)(wid * 32) * 128;   // uint4 index of warp's row 0

    for (int iter = 0; iter <= NITER; iter++) {
        // v into registers; lane's t-positions: t = 8*(lane+32*i)+j
        float vreg[32];
        if (iter > 0) {
            const float4* __restrict__ vs4 = (const float4*)v_s;
#pragma unroll
            for (int i = 0; i < 4; i++) {
                const float4 va = vs4[2 * (lane + 32 * i) + 0];
                const float4 vb = vs4[2 * (lane + 32 * i) + 1];
                vreg[8*i+0]=va.x; vreg[8*i+1]=va.y; vreg[8*i+2]=va.z; vreg[8*i+3]=va.w;
                vreg[8*i+4]=vb.x; vreg[8*i+5]=vb.y; vreg[8*i+6]=vb.z; vreg[8*i+7]=vb.w;
            }
        }

        float acc[32];
#pragma unroll
        for (int j = 0; j < 32; j++) acc[j] = 0.0f;

        // prefetch row 0
        uint4 k4[4];
#pragma unroll
        for (int i = 0; i < 4; i++) k4[i] = K4[row0 + lane + 32 * i];

#pragma unroll 4
        for (int rr = 0; rr < 32; rr++) {
            uint4 kn[4];
            if (rr < 31) {                 // prefetch next row
                const size_t nrow = row0 + (size_t)(rr + 1) * 128;
#pragma unroll
                for (int i = 0; i < 4; i++) kn[i] = K4[nrow + lane + 32 * i];
            }

            const unsigned int* hw = (const unsigned int*)k4;  // 16 bf16x2 words
            if (iter == 0) {
                // u = 1: accumulate K directly
#pragma unroll
                for (int q = 0; q < 16; q++) {
                    acc[2*q+0] += bf_lo(hw[q]);
                    acc[2*q+1] += bf_hi(hw[q]);
                }
            } else {
                // dot(K_p, v)
                float a = 0.0f;
#pragma unroll
                for (int q = 0; q < 16; q++) {
                    a += bf_lo(hw[q]) * vreg[2*q+0] + bf_hi(hw[q]) * vreg[2*q+1];
                }
#pragma unroll
                for (int o = 16; o; o >>= 1)
                    a += __shfl_xor_sync(0xFFFFFFFFu, a, o);

                const int p = wid * 32 + rr;
                const float up = __fdividef(pred_s[p], a);
                if (iter == NITER && lane == 0) u_s[p] = up;

                // accumulate u_p * K_p (re-convert; alu pipe, free)
#pragma unroll
                for (int q = 0; q < 16; q++) {
                    acc[2*q+0] += up * bf_lo(hw[q]);
                    acc[2*q+1] += up * bf_hi(hw[q]);
                }
            }
#pragma unroll
            for (int i = 0; i < 4; i++) k4[i] = kn[i];
        }

        // combine 16 warps -> buf[8][TT] (two rounds)
        if (wid < 8) {
            float4* __restrict__ dst = (float4*)&buf[wid][0];
#pragma unroll
            for (int i = 0; i < 4; i++) {
                const int idx = lane + 32 * i;
                dst[2*idx+0] = make_float4(acc[8*i+0], acc[8*i+1], acc[8*i+2], acc[8*i+3]);
                dst[2*idx+1] = make_float4(acc[8*i+4], acc[8*i+5], acc[8*i+6], acc[8*i+7]);
            }
        }
        __syncthreads();
        if (wid >= 8) {
            float4* __restrict__ dst = (float4*)&buf[wid - 8][0];
#pragma unroll
            for (int i = 0; i < 4; i++) {
                const int idx = lane + 32 * i;
                float4 x = dst[2*idx+0];
                x.x += acc[8*i+0]; x.y += acc[8*i+1]; x.z += acc[8*i+2]; x.w += acc[8*i+3];
                dst[2*idx+0] = x;
                float4 y = dst[2*idx+1];
                y.x += acc[8*i+4]; y.y += acc[8*i+5]; y.z += acc[8*i+6]; y.w += acc[8*i+7];
                dst[2*idx+1] = y;
            }
        }
        __syncthreads();

        float s0 = 0.0f, s1 = 0.0f;
#pragma unroll
        for (int k = 0; k < 8; k++) {
            s0 += buf[k][tid];
            s1 += buf[k][tid + 512];
        }

        // DSMEM exchange with peer CTA (parity double-buffer)
        const int par = iter & 1;
        {
            unsigned int l0 = (unsigned int)__cvta_generic_to_shared(&part_peer[par][tid]);
            unsigned int l1 = (unsigned int)__cvta_generic_to_shared(&part_peer[par][tid + 512]);
            unsigned int r0, r1;
            asm volatile("mapa.shared::cluster.u32 %0, %1, %2;" : "=r"(r0) : "r"(l0), "r"(peer));
            asm volatile("mapa.shared::cluster.u32 %0, %1, %2;" : "=r"(r1) : "r"(l1), "r"(peer));
            asm volatile("st.shared::cluster.f32 [%0], %1;" :: "r"(r0), "f"(s0) : "memory");
            asm volatile("st.shared::cluster.f32 [%0], %1;" :: "r"(r1), "f"(s1) : "memory");
        }
        asm volatile("barrier.cluster.arrive.aligned;" ::: "memory");
        asm volatile("barrier.cluster.wait.aligned;" ::: "memory");

        v_s[tid]       = tgt_a / (s0 + part_peer[par][tid]);
        v_s[tid + 512] = tgt_b / (s1 + part_peer[par][tid + 512]);
        __syncthreads();
    }

    g_u[b * PP + r * HALFP + tid] = u_s[tid];
    if (r == 0) {
        g_v[b * TT + tid]       = v_s[tid];
        g_v[b * TT + tid + 512] = v_s[tid + 512];
    }
}

// Final: P = u * exp(-C/reg) * v recomputed in fp32 from C
// (output never touches bf16 K). float4, 4 elems/thread.
__global__ void k_final(const float* __restrict__ C, const float* __restrict__ reg,
                        float* __restrict__ out) {
    const size_t i4 = (size_t)blockIdx.x * 256 + threadIdx.x;  // float4 index
    const float ninv = -1.0f / reg[0];
    const int row = (int)((i4 * 4) >> 10);     // b*1024 + p
    const int b   = row >> 10;
    const int t4  = (int)(i4 & 255);

    const float  u = g_u[row];
    const float4 c = ((const float4*)C)[i4];
    const float4 v = ((const float4*)(g_v + b * TT))[t4];

    float4 rv;
    rv.x = u * __expf(c.x * ninv) * v.x;
    rv.y = u * __expf(c.y * ninv) * v.y;
    rv.z = u * __expf(c.z * ninv) * v.z;
    rv.w = u * __expf(c.w * ninv) * v.w;
    ((float4*)out)[i4] = rv;
}

extern "C" void kernel_launch(void* const* d_in, const int* in_sizes, int n_in,
                              void* d_out, int out_size) {
    const float* pred = (const float*)d_in[0];
    const float* tgt  = (const float*)d_in[1];
    const float* C    = (const float*)d_in[2];
    const float* reg  = (const float*)d_in[3];
    float* out = (float*)d_out;

    const int n8 = (BB * PP * TT) / 8;
    const int n4 = (BB * PP * TT) / 4;

    k_exp<<<n8 / 256, 256>>>(C, reg);
    k_sinkhorn<<<2 * BB, 512>>>(pred, tgt);
    k_final<<<n4 / 256, 256>>>(C, reg, out);
}